// round 3
// baseline (speedup 1.0000x reference)
#include <cuda_runtime.h>
#include <cstdint>

// Problem constants
#define BATCH 4
#define C     128
#define H     64
#define W_    64
#define NPTS  9
#define HW    4096
#define KDIM  1152       // C*NPTS
#define NCOL  16384      // BATCH*HW
#define HP    66
#define WP    66

// GEMM tiling
#define BM 128
#define BN 64
#define BK 16
#define NIT 72           // KDIM / BK
#define AROW 136         // 128 + 8 pad (conflict-free LDS.64 frag loads)
#define BROW 72          // 64 + 8 pad  (q*8+g covers all 32 banks)

// Pre-permuted, tf32-converted weights: [NIT][16][128] in the exact As-tile
// image order (k-within-chunk major, m-permuted).
__device__ float g_wperm[NIT * 2048];

__device__ __forceinline__ uint32_t f2tf32(float f) {
    uint32_t r;
    asm("cvt.rna.tf32.f32 %0, %1;" : "=r"(r) : "f"(f));
    return r;
}

// ---------------------------------------------------------------------------
// Weight permute: g_wperm[kb][r][mp] = tf32(W[o(mp)][c*9+n]) with
// k' = kb*16+r = n*128+c, and mp = perm(o) pairing (j, j+8) adjacently.
// ---------------------------------------------------------------------------
__global__ void permute_w(const float* __restrict__ w) {
    int t = blockIdx.x * 256 + threadIdx.x;
    if (t >= NIT * 2048) return;
    int kb = t >> 11;
    int r  = (t >> 7) & 15;
    int mp = t & 127;
    int kk = kb * 16 + r;        // k' in n-major order
    int n = kk >> 7, c = kk & 127;
    int l = mp & 15;
    int o = (mp & ~15) | ((l & 1) << 3) | (l >> 1);   // inverse of perm
    g_wperm[t] = __uint_as_float(f2tf32(w[o * KDIM + c * 9 + n]));
}

// ---------------------------------------------------------------------------
// Fused deformable-sample + TF32 GEMM.
// Grid = NCOL/BN = 256 blocks, 256 threads (8 warps, 2(m) x 4(n)), 2 CTAs/SM.
// Each block: columns bn..bn+63 (one batch), all 128 output channels.
// K-loop (72 iters): stage Bs[16][64] by bilinear-gathering x directly,
// As[16][128] by straight copy from g_wperm. Double-buffered, reg-prefetched.
// ---------------------------------------------------------------------------
__global__ void __launch_bounds__(256, 2) fused_gemm(
    const float* __restrict__ x, const float* __restrict__ offset,
    float* __restrict__ out)
{
    __shared__ float As[2][BK][AROW];
    __shared__ float Bs[2][BK][BROW];
    __shared__ int4   sMi[NPTS * BN];
    __shared__ float4 sMw[NPTS * BN];

    int tid = threadIdx.x;
    int warp = tid >> 5, lane = tid & 31;
    int q = lane & 3, g = lane >> 2;
    int wm = warp >> 2, wn = warp & 3;

    int bn = blockIdx.x * BN;
    int b  = bn >> 12;
    int ij0 = bn & (HW - 1);

    // ---- inline sampling metadata for this block's 64 columns x 9 points ----
    for (int t = tid; t < NPTS * BN; t += 256) {
        int n = t >> 6;
        int col = t & 63;
        int ij = ij0 + col;
        int i = ij >> 6, j = ij & 63;

        float offx = offset[((b * 18) + 2 * n) * HW + ij];
        float offy = offset[((b * 18) + 2 * n + 1) * HW + ij];

        float px = (float)(i + 1) + (float)(n / 3 - 1) + offx;
        float py = (float)(j + 1) + (float)(n % 3 - 1) + offy;

        float fx = floorf(px), fy = floorf(py);
        float qltx = fminf(fmaxf(fx, 0.f), (float)(HP - 1));
        float qlty = fminf(fmaxf(fy, 0.f), (float)(WP - 1));
        float qrbx = fminf(fmaxf(fx + 1.f, 0.f), (float)(HP - 1));
        float qrby = fminf(fmaxf(fy + 1.f, 0.f), (float)(WP - 1));

        if (px < 1.f || px > (float)(HP - 2)) px = fx;
        if (py < 1.f || py > (float)(WP - 2)) py = fy;
        px = fminf(fmaxf(px, 0.f), (float)(HP - 1));
        py = fminf(fmaxf(py, 0.f), (float)(WP - 1));

        float glt = (1.f + (qltx - px)) * (1.f + (qlty - py));
        float grb = (1.f - (qrbx - px)) * (1.f - (qrby - py));
        float glb = (1.f + (qltx - px)) * (1.f - (qrby - py));
        float grt = (1.f - (qrbx - px)) * (1.f + (qlty - py));

        int ltx = (int)qltx, lty = (int)qlty, rbx = (int)qrbx, rby = (int)qrby;
        int4 id;
        float4 w = make_float4(glt, grb, glb, grt);
        {
            bool v = (ltx >= 1 && ltx <= H && lty >= 1 && lty <= W_);
            id.x = v ? ((ltx - 1) << 6) + (lty - 1) : 0;
            if (!v) w.x = 0.f;
        }
        {
            bool v = (rbx >= 1 && rbx <= H && rby >= 1 && rby <= W_);
            id.y = v ? ((rbx - 1) << 6) + (rby - 1) : 0;
            if (!v) w.y = 0.f;
        }
        {
            bool v = (ltx >= 1 && ltx <= H && rby >= 1 && rby <= W_);
            id.z = v ? ((ltx - 1) << 6) + (rby - 1) : 0;
            if (!v) w.z = 0.f;
        }
        {
            bool v = (rbx >= 1 && rbx <= H && lty >= 1 && lty <= W_);
            id.w = v ? ((rbx - 1) << 6) + (lty - 1) : 0;
            if (!v) w.w = 0.f;
        }
        sMi[t] = id;
        sMw[t] = w;
    }
    __syncthreads();

    // staging thread maps
    int ar = tid >> 4;            // As row (k in chunk)
    int ac8 = (tid & 15) * 8;     // As col start
    int bcl = tid >> 4;           // Bs row = c_local
    int col0 = (tid & 15) * 4;    // 4 columns per thread

    float acc[4][2][4];
#pragma unroll
    for (int mt = 0; mt < 4; mt++)
#pragma unroll
        for (int nt = 0; nt < 2; nt++)
#pragma unroll
            for (int r = 0; r < 4; r++) acc[mt][nt][r] = 0.f;

    // prefetch registers
    float4 ra0, ra1;
    float tap[4][4];

    // ---- LOAD(it=0) ----
    {
        const float* asrc = g_wperm + 0 * 2048 + ar * 128 + ac8;
        ra0 = *(const float4*)asrc;
        ra1 = *(const float4*)(asrc + 4);
        int c = bcl;              // it=0: n=0, c0=0
        const float* pl = x + (size_t)(((b << 7) + c) << 12);
#pragma unroll
        for (int jj = 0; jj < 4; jj++) {
            int4 id = sMi[col0 + jj];
            tap[jj][0] = __ldg(&pl[id.x]);
            tap[jj][1] = __ldg(&pl[id.y]);
            tap[jj][2] = __ldg(&pl[id.z]);
            tap[jj][3] = __ldg(&pl[id.w]);
        }
    }

    for (int it = 0; it < NIT; it++) {
        int p = it & 1;
        // ---- STORE staged regs to smem ----
        *(float4*)&As[p][ar][ac8] = ra0;
        *(float4*)&As[p][ar][ac8 + 4] = ra1;
        {
            int n = it >> 3;
            float v[4];
#pragma unroll
            for (int jj = 0; jj < 4; jj++) {
                float4 w = sMw[n * 64 + col0 + jj];
                float s = w.x * tap[jj][0] + w.y * tap[jj][1] +
                          w.z * tap[jj][2] + w.w * tap[jj][3];
                v[jj] = __uint_as_float(f2tf32(s));
            }
            *(float4*)&Bs[p][bcl][col0] = make_float4(v[0], v[1], v[2], v[3]);
        }
        __syncthreads();

        // ---- prefetch next iter ----
        if (it + 1 < NIT) {
            int it1 = it + 1;
            const float* asrc = g_wperm + (size_t)it1 * 2048 + ar * 128 + ac8;
            ra0 = *(const float4*)asrc;
            ra1 = *(const float4*)(asrc + 4);
            int n1 = it1 >> 3;
            int c = ((it1 & 7) << 4) + bcl;
            const float* pl = x + (size_t)(((b << 7) + c) << 12);
#pragma unroll
            for (int jj = 0; jj < 4; jj++) {
                int4 id = sMi[n1 * 64 + col0 + jj];
                tap[jj][0] = __ldg(&pl[id.x]);
                tap[jj][1] = __ldg(&pl[id.y]);
                tap[jj][2] = __ldg(&pl[id.z]);
                tap[jj][3] = __ldg(&pl[id.w]);
            }
        }

        // ---- MMA over buffer p ----
#pragma unroll
        for (int ks = 0; ks < 2; ks++) {
            int k0 = ks * 8;
            uint32_t a[4][4], bb[2][2];
#pragma unroll
            for (int mt = 0; mt < 4; mt++) {
                int mbase = (wm * 4 + mt) * 16 + g * 2;
                float2 p0 = *(float2*)&As[p][k0 + q][mbase];
                float2 p1 = *(float2*)&As[p][k0 + q + 4][mbase];
                a[mt][0] = __float_as_uint(p0.x);
                a[mt][1] = __float_as_uint(p0.y);
                a[mt][2] = __float_as_uint(p1.x);
                a[mt][3] = __float_as_uint(p1.y);
            }
#pragma unroll
            for (int nt = 0; nt < 2; nt++) {
                int nb = wn * 16 + nt * 8 + g;
                bb[nt][0] = __float_as_uint(Bs[p][k0 + q][nb]);
                bb[nt][1] = __float_as_uint(Bs[p][k0 + q + 4][nb]);
            }
#pragma unroll
            for (int mt = 0; mt < 4; mt++)
#pragma unroll
                for (int nt = 0; nt < 2; nt++) {
                    asm volatile(
                        "mma.sync.aligned.m16n8k8.row.col.f32.tf32.tf32.f32 "
                        "{%0,%1,%2,%3}, {%4,%5,%6,%7}, {%8,%9}, {%0,%1,%2,%3};"
                        : "+f"(acc[mt][nt][0]), "+f"(acc[mt][nt][1]),
                          "+f"(acc[mt][nt][2]), "+f"(acc[mt][nt][3])
                        : "r"(a[mt][0]), "r"(a[mt][1]), "r"(a[mt][2]), "r"(a[mt][3]),
                          "r"(bb[nt][0]), "r"(bb[nt][1]));
                }
        }
        // no second sync: double-buffered
    }

    // ---- epilogue ----
#pragma unroll
    for (int mt = 0; mt < 4; mt++) {
#pragma unroll
        for (int nt = 0; nt < 2; nt++) {
            int ng = bn + wn * 16 + nt * 8 + 2 * q;
            int ij = ng & (HW - 1);
            int m0 = wm * 64 + mt * 16 + g;
            *(float2*)&out[(size_t)(((b << 7) + m0) << 12) + ij] =
                make_float2(acc[mt][nt][0], acc[mt][nt][1]);
            *(float2*)&out[(size_t)(((b << 7) + m0 + 8) << 12) + ij] =
                make_float2(acc[mt][nt][2], acc[mt][nt][3]);
        }
    }
}

// ---------------------------------------------------------------------------
extern "C" void kernel_launch(void* const* d_in, const int* in_sizes, int n_in,
                              void* d_out, int out_size) {
    const float* x      = (const float*)d_in[0];   // (4,128,64,64)
    const float* offset = (const float*)d_in[1];   // (4,18,64,64)
    const float* weight = (const float*)d_in[2];   // (128,128,3,3)
    float* out = (float*)d_out;                    // (4,128,64,64)

    (void)in_sizes; (void)n_in; (void)out_size;

    permute_w<<<(NIT * 2048 + 255) / 256, 256>>>(weight);
    fused_gemm<<<NCOL / BN, 256>>>(x, offset, out);
}

// round 4
// speedup vs baseline: 2.1073x; 2.1073x over previous
#include <cuda_runtime.h>
#include <cstdint>

// Problem constants
#define BATCH 4
#define C     128
#define H     64
#define W_    64
#define NPTS  9
#define HW    4096
#define KDIM  1152       // C*NPTS
#define NCOL  16384      // BATCH*HW
#define HP    66
#define WP    66

// GEMM tiling
#define BM 128
#define BN 64
#define BK 16
#define NIT 72           // KDIM / BK
#define AROW 136         // 128 + 8 pad
#define BROW 72          // 64 + 8 pad

// Pre-permuted tf32 weights: [NIT][16][128], k' = n*128 + c, m permuted.
__device__ float g_wperm[NIT * 2048];
// Channels-last x: g_xT[b][ij][c]
__device__ float g_xT[BATCH * HW * C];

__device__ __forceinline__ uint32_t f2tf32(float f) {
    uint32_t r;
    asm("cvt.rna.tf32.f32 %0, %1;" : "=r"(r) : "f"(f));
    return r;
}

// ---------------------------------------------------------------------------
// Weight permute (k' = n*128+c ordering, m-pair permutation).
// ---------------------------------------------------------------------------
__global__ void permute_w(const float* __restrict__ w) {
    int t = blockIdx.x * 256 + threadIdx.x;
    if (t >= NIT * 2048) return;
    int kb = t >> 11;
    int r  = (t >> 7) & 15;
    int mp = t & 127;
    int kk = kb * 16 + r;
    int n = kk >> 7, c = kk & 127;
    int l = mp & 15;
    int o = (mp & ~15) | ((l & 1) << 3) | (l >> 1);
    g_wperm[t] = __uint_as_float(f2tf32(w[o * KDIM + c * 9 + n]));
}

// ---------------------------------------------------------------------------
// Transpose x (b,c,ij) -> g_xT (b,ij,c). 32x32 tiles, smem staging.
// grid = (HW/32, C/32, BATCH), block = (32,8)
// ---------------------------------------------------------------------------
__global__ void transpose_x(const float* __restrict__ x) {
    __shared__ float tile[32][33];
    int ij0 = blockIdx.x * 32;
    int c0  = blockIdx.y * 32;
    int b   = blockIdx.z;
    const float* src = x + (size_t)b * C * HW;
    float* dst = g_xT + (size_t)b * HW * C;
#pragma unroll
    for (int r = 0; r < 32; r += 8) {
        int c = c0 + threadIdx.y + r;
        tile[threadIdx.y + r][threadIdx.x] = src[(size_t)c * HW + ij0 + threadIdx.x];
    }
    __syncthreads();
#pragma unroll
    for (int r = 0; r < 32; r += 8) {
        int ij = ij0 + threadIdx.y + r;
        dst[(size_t)ij * C + c0 + threadIdx.x] = tile[threadIdx.x][threadIdx.y + r];
    }
}

// ---------------------------------------------------------------------------
// Fused deformable-sample + TF32 GEMM, channels-last gathers.
// Grid = 256 blocks (all resident), 256 threads, 2 CTAs/SM.
// B-stage: thread (col = tid>>2, cq = (tid&3)*4) loads one float4 per tap
// from g_xT (contiguous channels) and blends with bilinear weights.
// ---------------------------------------------------------------------------
__global__ void __launch_bounds__(256, 2) fused_gemm(
    const float* __restrict__ offset, float* __restrict__ out)
{
    __shared__ float As[2][BK][AROW];
    __shared__ float Bs[2][BK][BROW];
    __shared__ int4   sMi[NPTS * BN];
    __shared__ float4 sMw[NPTS * BN];

    int tid = threadIdx.x;
    int warp = tid >> 5, lane = tid & 31;
    int q = lane & 3, g = lane >> 2;
    int wm = warp >> 2, wn = warp & 3;

    int bn = blockIdx.x * BN;
    int b  = bn >> 12;
    int ij0 = bn & (HW - 1);

    // ---- sampling metadata: 9 points x 64 columns ----
    for (int t = tid; t < NPTS * BN; t += 256) {
        int n = t >> 6;
        int col = t & 63;
        int ij = ij0 + col;
        int i = ij >> 6, j = ij & 63;

        float offx = offset[((b * 18) + 2 * n) * HW + ij];
        float offy = offset[((b * 18) + 2 * n + 1) * HW + ij];

        float px = (float)(i + 1) + (float)(n / 3 - 1) + offx;
        float py = (float)(j + 1) + (float)(n % 3 - 1) + offy;

        float fx = floorf(px), fy = floorf(py);
        float qltx = fminf(fmaxf(fx, 0.f), (float)(HP - 1));
        float qlty = fminf(fmaxf(fy, 0.f), (float)(WP - 1));
        float qrbx = fminf(fmaxf(fx + 1.f, 0.f), (float)(HP - 1));
        float qrby = fminf(fmaxf(fy + 1.f, 0.f), (float)(WP - 1));

        if (px < 1.f || px > (float)(HP - 2)) px = fx;
        if (py < 1.f || py > (float)(WP - 2)) py = fy;
        px = fminf(fmaxf(px, 0.f), (float)(HP - 1));
        py = fminf(fmaxf(py, 0.f), (float)(WP - 1));

        float glt = (1.f + (qltx - px)) * (1.f + (qlty - py));
        float grb = (1.f - (qrbx - px)) * (1.f - (qrby - py));
        float glb = (1.f + (qltx - px)) * (1.f - (qrby - py));
        float grt = (1.f - (qrbx - px)) * (1.f + (qlty - py));

        int ltx = (int)qltx, lty = (int)qlty, rbx = (int)qrbx, rby = (int)qrby;
        int4 id;
        float4 w = make_float4(glt, grb, glb, grt);
        {
            bool v = (ltx >= 1 && ltx <= H && lty >= 1 && lty <= W_);
            id.x = v ? ((ltx - 1) << 6) + (lty - 1) : 0;
            if (!v) w.x = 0.f;
        }
        {
            bool v = (rbx >= 1 && rbx <= H && rby >= 1 && rby <= W_);
            id.y = v ? ((rbx - 1) << 6) + (rby - 1) : 0;
            if (!v) w.y = 0.f;
        }
        {
            bool v = (ltx >= 1 && ltx <= H && rby >= 1 && rby <= W_);
            id.z = v ? ((ltx - 1) << 6) + (rby - 1) : 0;
            if (!v) w.z = 0.f;
        }
        {
            bool v = (rbx >= 1 && rbx <= H && lty >= 1 && lty <= W_);
            id.w = v ? ((rbx - 1) << 6) + (lty - 1) : 0;
            if (!v) w.w = 0.f;
        }
        sMi[t] = id;
        sMw[t] = w;
    }
    __syncthreads();

    // staging maps
    int ar = tid >> 4;            // As row
    int ac8 = (tid & 15) * 8;     // As col start
    int bcol = tid >> 2;          // Bs column (0..63): lane<->column 1:1 in quads
    int cq = (tid & 3) * 4;       // channel quad within BK

    const float* xb = g_xT + ((size_t)b << 12) * C;

    float acc[4][2][4];
#pragma unroll
    for (int mt = 0; mt < 4; mt++)
#pragma unroll
        for (int nt = 0; nt < 2; nt++)
#pragma unroll
            for (int r = 0; r < 4; r++) acc[mt][nt][r] = 0.f;

    float4 ra0, ra1;
    float4 tap[4];
    float4 wgt;

    // ---- LOAD(it=0): n=0, c0=0 ----
    {
        const float* asrc = g_wperm + ar * 128 + ac8;
        ra0 = *(const float4*)asrc;
        ra1 = *(const float4*)(asrc + 4);
        int4 id = sMi[bcol];
        wgt = sMw[bcol];
        tap[0] = *(const float4*)(xb + ((size_t)id.x << 7) + cq);
        tap[1] = *(const float4*)(xb + ((size_t)id.y << 7) + cq);
        tap[2] = *(const float4*)(xb + ((size_t)id.z << 7) + cq);
        tap[3] = *(const float4*)(xb + ((size_t)id.w << 7) + cq);
    }

    for (int it = 0; it < NIT; it++) {
        int p = it & 1;
        // ---- STORE staged to smem ----
        *(float4*)&As[p][ar][ac8] = ra0;
        *(float4*)&As[p][ar][ac8 + 4] = ra1;
        {
            float v0 = wgt.x * tap[0].x + wgt.y * tap[1].x + wgt.z * tap[2].x + wgt.w * tap[3].x;
            float v1 = wgt.x * tap[0].y + wgt.y * tap[1].y + wgt.z * tap[2].y + wgt.w * tap[3].y;
            float v2 = wgt.x * tap[0].z + wgt.y * tap[1].z + wgt.z * tap[2].z + wgt.w * tap[3].z;
            float v3 = wgt.x * tap[0].w + wgt.y * tap[1].w + wgt.z * tap[2].w + wgt.w * tap[3].w;
            Bs[p][cq + 0][bcol] = __uint_as_float(f2tf32(v0));
            Bs[p][cq + 1][bcol] = __uint_as_float(f2tf32(v1));
            Bs[p][cq + 2][bcol] = __uint_as_float(f2tf32(v2));
            Bs[p][cq + 3][bcol] = __uint_as_float(f2tf32(v3));
        }
        __syncthreads();

        // ---- prefetch next tile ----
        if (it + 1 < NIT) {
            int it1 = it + 1;
            const float* asrc = g_wperm + (size_t)it1 * 2048 + ar * 128 + ac8;
            ra0 = *(const float4*)asrc;
            ra1 = *(const float4*)(asrc + 4);
            int n1 = it1 >> 3;
            int c0 = ((it1 & 7) << 4) + cq;
            int4 id = sMi[n1 * 64 + bcol];
            wgt = sMw[n1 * 64 + bcol];
            tap[0] = *(const float4*)(xb + ((size_t)id.x << 7) + c0);
            tap[1] = *(const float4*)(xb + ((size_t)id.y << 7) + c0);
            tap[2] = *(const float4*)(xb + ((size_t)id.z << 7) + c0);
            tap[3] = *(const float4*)(xb + ((size_t)id.w << 7) + c0);
        }

        // ---- MMA over buffer p ----
#pragma unroll
        for (int ks = 0; ks < 2; ks++) {
            int k0 = ks * 8;
            uint32_t a[4][4], bb[2][2];
#pragma unroll
            for (int mt = 0; mt < 4; mt++) {
                int mbase = (wm * 4 + mt) * 16 + g * 2;
                float2 p0 = *(float2*)&As[p][k0 + q][mbase];
                float2 p1 = *(float2*)&As[p][k0 + q + 4][mbase];
                a[mt][0] = __float_as_uint(p0.x);
                a[mt][1] = __float_as_uint(p0.y);
                a[mt][2] = __float_as_uint(p1.x);
                a[mt][3] = __float_as_uint(p1.y);
            }
#pragma unroll
            for (int nt = 0; nt < 2; nt++) {
                int nb = wn * 16 + nt * 8 + g;
                bb[nt][0] = __float_as_uint(Bs[p][k0 + q][nb]);
                bb[nt][1] = __float_as_uint(Bs[p][k0 + q + 4][nb]);
            }
#pragma unroll
            for (int mt = 0; mt < 4; mt++)
#pragma unroll
                for (int nt = 0; nt < 2; nt++) {
                    asm volatile(
                        "mma.sync.aligned.m16n8k8.row.col.f32.tf32.tf32.f32 "
                        "{%0,%1,%2,%3}, {%4,%5,%6,%7}, {%8,%9}, {%0,%1,%2,%3};"
                        : "+f"(acc[mt][nt][0]), "+f"(acc[mt][nt][1]),
                          "+f"(acc[mt][nt][2]), "+f"(acc[mt][nt][3])
                        : "r"(a[mt][0]), "r"(a[mt][1]), "r"(a[mt][2]), "r"(a[mt][3]),
                          "r"(bb[nt][0]), "r"(bb[nt][1]));
                }
        }
    }

    // ---- epilogue ----
#pragma unroll
    for (int mt = 0; mt < 4; mt++) {
#pragma unroll
        for (int nt = 0; nt < 2; nt++) {
            int ng = bn + wn * 16 + nt * 8 + 2 * q;
            int ij = ng & (HW - 1);
            int m0 = wm * 64 + mt * 16 + g;
            *(float2*)&out[(size_t)(((b << 7) + m0) << 12) + ij] =
                make_float2(acc[mt][nt][0], acc[mt][nt][1]);
            *(float2*)&out[(size_t)(((b << 7) + m0 + 8) << 12) + ij] =
                make_float2(acc[mt][nt][2], acc[mt][nt][3]);
        }
    }
}

// ---------------------------------------------------------------------------
extern "C" void kernel_launch(void* const* d_in, const int* in_sizes, int n_in,
                              void* d_out, int out_size) {
    const float* x      = (const float*)d_in[0];
    const float* offset = (const float*)d_in[1];
    const float* weight = (const float*)d_in[2];
    float* out = (float*)d_out;

    (void)in_sizes; (void)n_in; (void)out_size;

    permute_w<<<(NIT * 2048 + 255) / 256, 256>>>(weight);
    dim3 gt(HW / 32, C / 32, BATCH);
    transpose_x<<<gt, dim3(32, 8)>>>(x);
    fused_gemm<<<NCOL / BN, 256>>>(offset, out);
}

// round 7
// speedup vs baseline: 2.1506x; 1.0205x over previous
#include <cuda_runtime.h>
#include <cstdint>

// Problem constants
#define BATCH 4
#define C     128
#define H     64
#define W_    64
#define NPTS  9
#define HW    4096
#define KDIM  1152
#define NCOL  16384
#define HP    66
#define WP    66

// GEMM tiling
#define BM 128
#define BN 64
#define BK 16
#define NIT 72           // KDIM / BK
#define AROW 136         // 128 + 8 pad (As: [k][perm(m)])
#define BSTR 20          // Bs: [n][k] stride 16+4 -> conflict-free

__device__ float g_wperm[NIT * 2048];
__device__ float g_xT[BATCH * HW * C];

__device__ __forceinline__ uint32_t f2tf32(float f) {
    uint32_t r;
    asm("cvt.rna.tf32.f32 %0, %1;" : "=r"(r) : "f"(f));
    return r;
}

// ---------------------------------------------------------------------------
// Prep: blocks [0,2048) transpose x -> channels-last; blocks [2048,2624)
// permute weights into the As-tile image (tf32, k' = n*128+c, m-pair perm).
// ---------------------------------------------------------------------------
__global__ void __launch_bounds__(256) prep_kernel(const float* __restrict__ x,
                                                   const float* __restrict__ w) {
    if (blockIdx.x < 2048) {
        __shared__ float tile[32][33];
        int blk = blockIdx.x;
        int bx = blk & 127;          // HW/32 = 128
        int by = (blk >> 7) & 3;     // C/32 = 4
        int b  = blk >> 9;           // batch
        int ij0 = bx * 32, c0 = by * 32;
        int tx = threadIdx.x & 31, ty = threadIdx.x >> 5;   // (32,8)
        const float* src = x + (size_t)b * C * HW;
        float* dst = g_xT + (size_t)b * HW * C;
#pragma unroll
        for (int r = 0; r < 32; r += 8)
            tile[ty + r][tx] = src[(size_t)(c0 + ty + r) * HW + ij0 + tx];
        __syncthreads();
#pragma unroll
        for (int r = 0; r < 32; r += 8)
            dst[(size_t)(ij0 + ty + r) * C + c0 + tx] = tile[tx][ty + r];
    } else {
        int t = (blockIdx.x - 2048) * 256 + threadIdx.x;
        if (t >= NIT * 2048) return;
        int kb = t >> 11;
        int r  = (t >> 7) & 15;
        int mp = t & 127;
        int kk = kb * 16 + r;
        int n = kk >> 7, c = kk & 127;
        int l = mp & 15;
        int o = (mp & ~15) | ((l & 1) << 3) | (l >> 1);
        g_wperm[t] = __uint_as_float(f2tf32(w[o * KDIM + c * 9 + n]));
    }
}

// ---------------------------------------------------------------------------
// Fused deformable-sample + TF32 GEMM.
// As: cp.async 3-deep ring, issued 2 iters ahead. Bs: register-prefetched
// gathers (channels-last), n-major smem layout, STS.128 conflict-free.
// ---------------------------------------------------------------------------
__global__ void __launch_bounds__(256, 2) fused_gemm(
    const float* __restrict__ offset, float* __restrict__ out)
{
    __shared__ float As[3][BK][AROW];
    __shared__ float Bs[2][BN * BSTR];
    __shared__ int4   sMi[NPTS * BN];
    __shared__ float4 sMw[NPTS * BN];

    int tid = threadIdx.x;
    int warp = tid >> 5, lane = tid & 31;
    int q = lane & 3, g = lane >> 2;
    int wm = warp >> 2, wn = warp & 3;

    int bn = blockIdx.x * BN;
    int b  = bn >> 12;
    int ij0 = bn & (HW - 1);

    // ---- sampling metadata ----
    for (int t = tid; t < NPTS * BN; t += 256) {
        int n = t >> 6;
        int col = t & 63;
        int ij = ij0 + col;
        int i = ij >> 6, j = ij & 63;

        float offx = offset[((b * 18) + 2 * n) * HW + ij];
        float offy = offset[((b * 18) + 2 * n + 1) * HW + ij];

        float px = (float)(i + 1) + (float)(n / 3 - 1) + offx;
        float py = (float)(j + 1) + (float)(n % 3 - 1) + offy;

        float fx = floorf(px), fy = floorf(py);
        float qltx = fminf(fmaxf(fx, 0.f), (float)(HP - 1));
        float qlty = fminf(fmaxf(fy, 0.f), (float)(WP - 1));
        float qrbx = fminf(fmaxf(fx + 1.f, 0.f), (float)(HP - 1));
        float qrby = fminf(fmaxf(fy + 1.f, 0.f), (float)(WP - 1));

        if (px < 1.f || px > (float)(HP - 2)) px = fx;
        if (py < 1.f || py > (float)(WP - 2)) py = fy;
        px = fminf(fmaxf(px, 0.f), (float)(HP - 1));
        py = fminf(fmaxf(py, 0.f), (float)(WP - 1));

        float glt = (1.f + (qltx - px)) * (1.f + (qlty - py));
        float grb = (1.f - (qrbx - px)) * (1.f - (qrby - py));
        float glb = (1.f + (qltx - px)) * (1.f - (qrby - py));
        float grt = (1.f - (qrbx - px)) * (1.f + (qlty - py));

        int ltx = (int)qltx, lty = (int)qlty, rbx = (int)qrbx, rby = (int)qrby;
        int4 id;
        float4 wv = make_float4(glt, grb, glb, grt);
        {
            bool v = (ltx >= 1 && ltx <= H && lty >= 1 && lty <= W_);
            id.x = v ? ((ltx - 1) << 6) + (lty - 1) : 0;
            if (!v) wv.x = 0.f;
        }
        {
            bool v = (rbx >= 1 && rbx <= H && rby >= 1 && rby <= W_);
            id.y = v ? ((rbx - 1) << 6) + (rby - 1) : 0;
            if (!v) wv.y = 0.f;
        }
        {
            bool v = (ltx >= 1 && ltx <= H && rby >= 1 && rby <= W_);
            id.z = v ? ((ltx - 1) << 6) + (rby - 1) : 0;
            if (!v) wv.z = 0.f;
        }
        {
            bool v = (rbx >= 1 && rbx <= H && lty >= 1 && lty <= W_);
            id.w = v ? ((rbx - 1) << 6) + (lty - 1) : 0;
            if (!v) wv.w = 0.f;
        }
        sMi[t] = id;
        sMw[t] = wv;
    }
    __syncthreads();

    // staging maps
    int ar = tid >> 4;                 // As row
    int ac8 = (tid & 15) * 8;          // As col start
    int bcol = tid >> 2;               // Bs column 0..63
    int cq = (tid & 3) * 4;            // channel quad

    const float* xb = g_xT + (((size_t)b << 12) << 7);

    // cp.async smem byte addresses for the 3 As buffers
    uint32_t asm0 = (uint32_t)__cvta_generic_to_shared(&As[0][ar][ac8]);
    uint32_t asm1 = (uint32_t)__cvta_generic_to_shared(&As[1][ar][ac8]);
    uint32_t asm2 = (uint32_t)__cvta_generic_to_shared(&As[2][ar][ac8]);
    uint32_t asmv[3] = {asm0, asm1, asm2};
    const float* agbase = g_wperm + ar * 128 + ac8;

#define CP16(sa, ga) asm volatile("cp.async.ca.shared.global [%0], [%1], 16;" :: "r"(sa), "l"(ga))
#define CPCOMMIT()   asm volatile("cp.async.commit_group;")
#define CPWAIT1()    asm volatile("cp.async.wait_group 1;")

    float acc[4][2][4];
#pragma unroll
    for (int mt = 0; mt < 4; mt++)
#pragma unroll
        for (int nt = 0; nt < 2; nt++)
#pragma unroll
            for (int r = 0; r < 4; r++) acc[mt][nt][r] = 0.f;

    float4 tap[4];
    float4 wgt;

    // ---- prologue: A for it=0,1 via cp.async; B taps for it=0 ----
    CP16(asmv[0], agbase);
    CP16(asmv[0] + 16, agbase + 4);
    CPCOMMIT();
    CP16(asmv[1], agbase + 2048);
    CP16(asmv[1] + 16, agbase + 2048 + 4);
    CPCOMMIT();
    {
        int4 id = sMi[bcol];
        wgt = sMw[bcol];
        tap[0] = *(const float4*)(xb + ((size_t)id.x << 7) + cq);
        tap[1] = *(const float4*)(xb + ((size_t)id.y << 7) + cq);
        tap[2] = *(const float4*)(xb + ((size_t)id.z << 7) + cq);
        tap[3] = *(const float4*)(xb + ((size_t)id.w << 7) + cq);
    }

    for (int it = 0; it < NIT; it++) {
        int pb = it & 1;
        int pa = it % 3;

        // ---- blend + store Bs (STS.128, conflict-free) ----
        {
            float v0 = wgt.x * tap[0].x + wgt.y * tap[1].x + wgt.z * tap[2].x + wgt.w * tap[3].x;
            float v1 = wgt.x * tap[0].y + wgt.y * tap[1].y + wgt.z * tap[2].y + wgt.w * tap[3].y;
            float v2 = wgt.x * tap[0].z + wgt.y * tap[1].z + wgt.z * tap[2].z + wgt.w * tap[3].z;
            float v3 = wgt.x * tap[0].w + wgt.y * tap[1].w + wgt.z * tap[2].w + wgt.w * tap[3].w;
            *(float4*)&Bs[pb][bcol * BSTR + cq] = make_float4(
                __uint_as_float(f2tf32(v0)), __uint_as_float(f2tf32(v1)),
                __uint_as_float(f2tf32(v2)), __uint_as_float(f2tf32(v3)));
        }

        // ---- prefetch B taps for it+1 ----
        if (it + 1 < NIT) {
            int it1 = it + 1;
            int n1 = it1 >> 3;
            int c0 = ((it1 & 7) << 4) + cq;
            int4 id = sMi[n1 * 64 + bcol];
            wgt = sMw[n1 * 64 + bcol];
            tap[0] = *(const float4*)(xb + ((size_t)id.x << 7) + c0);
            tap[1] = *(const float4*)(xb + ((size_t)id.y << 7) + c0);
            tap[2] = *(const float4*)(xb + ((size_t)id.z << 7) + c0);
            tap[3] = *(const float4*)(xb + ((size_t)id.w << 7) + c0);
        }

        CPWAIT1();
        __syncthreads();

        // ---- issue A copy for it+2 (post-sync: no hazard vs lagging MMA) ----
        if (it + 2 < NIT) {
            uint32_t sa = asmv[(it + 2) % 3];
            const float* ga = agbase + (size_t)(it + 2) * 2048;
            CP16(sa, ga);
            CP16(sa + 16, ga + 4);
        }
        CPCOMMIT();

        // ---- MMA ----
#pragma unroll
        for (int ks = 0; ks < 2; ks++) {
            int k0 = ks * 8;
            uint32_t a[4][4], bb[2][2];
#pragma unroll
            for (int mt = 0; mt < 4; mt++) {
                int mbase = (wm * 4 + mt) * 16 + g * 2;
                float2 p0 = *(float2*)&As[pa][k0 + q][mbase];
                float2 p1 = *(float2*)&As[pa][k0 + q + 4][mbase];
                a[mt][0] = __float_as_uint(p0.x);
                a[mt][1] = __float_as_uint(p0.y);
                a[mt][2] = __float_as_uint(p1.x);
                a[mt][3] = __float_as_uint(p1.y);
            }
#pragma unroll
            for (int nt = 0; nt < 2; nt++) {
                int nb = wn * 16 + nt * 8 + g;
                bb[nt][0] = __float_as_uint(Bs[pb][nb * BSTR + k0 + q]);
                bb[nt][1] = __float_as_uint(Bs[pb][nb * BSTR + k0 + q + 4]);
            }
#pragma unroll
            for (int mt = 0; mt < 4; mt++)
#pragma unroll
                for (int nt = 0; nt < 2; nt++) {
                    asm volatile(
                        "mma.sync.aligned.m16n8k8.row.col.f32.tf32.tf32.f32 "
                        "{%0,%1,%2,%3}, {%4,%5,%6,%7}, {%8,%9}, {%0,%1,%2,%3};"
                        : "+f"(acc[mt][nt][0]), "+f"(acc[mt][nt][1]),
                          "+f"(acc[mt][nt][2]), "+f"(acc[mt][nt][3])
                        : "r"(a[mt][0]), "r"(a[mt][1]), "r"(a[mt][2]), "r"(a[mt][3]),
                          "r"(bb[nt][0]), "r"(bb[nt][1]));
                }
        }
    }

    // ---- epilogue ----
#pragma unroll
    for (int mt = 0; mt < 4; mt++) {
#pragma unroll
        for (int nt = 0; nt < 2; nt++) {
            int ng = bn + wn * 16 + nt * 8 + 2 * q;
            int ij = ng & (HW - 1);
            int m0 = wm * 64 + mt * 16 + g;
            *(float2*)&out[(size_t)(((b << 7) + m0) << 12) + ij] =
                make_float2(acc[mt][nt][0], acc[mt][nt][1]);
            *(float2*)&out[(size_t)(((b << 7) + m0 + 8) << 12) + ij] =
                make_float2(acc[mt][nt][2], acc[mt][nt][3]);
        }
    }
}

// ---------------------------------------------------------------------------
extern "C" void kernel_launch(void* const* d_in, const int* in_sizes, int n_in,
                              void* d_out, int out_size) {
    const float* x      = (const float*)d_in[0];
    const float* offset = (const float*)d_in[1];
    const float* weight = (const float*)d_in[2];
    float* out = (float*)d_out;

    (void)in_sizes; (void)n_in; (void)out_size;

    prep_kernel<<<2048 + (NIT * 2048 + 255) / 256, 256>>>(x, weight);
    fused_gemm<<<NCOL / BN, 256>>>(offset, out);
}